// round 10
// baseline (speedup 1.0000x reference)
#include <cuda_runtime.h>
#include <cuda_bf16.h>

// Gram-Schmidt over M=4 model outputs, per (batch, channel) vector of D=1024.
// x: [4, 128, 64, 1024] fp32, out same shape.
//
// R2:  all 10 pairwise dots G_ij in ONE fused block reduction; GS coefficients
//      are scalar algebra on G (lower-triangular T, basis_i = sum_j T_ij v_j).
// R5:  32-bit byte addressing; occupancy proven insensitive (46-68% -> flat).
// R8/9: L2 policy hints proven inert -> removed.
// R10: 256-bit memory ops (sm_100 LDG.256/STG.256 via ld/st.global.v8.b32).
//      128 threads/CTA, 32B per thread per vector: halves memory-instruction
//      count and L1tex queue entries per byte, 1KB contiguous per warp-load
//      for longer DRAM bursts, halves reduction warps (4) and barrier cost.

#define NTHREADS 128
#define D_DIM 1024
#define NPAIRS 8192              // B*C
#define MSTRIDE_B 33554432u      // B*C*D*4 bytes = 32 MB

struct f8 { float4 a, b; };

__device__ __forceinline__ f8 ldg256(const void* p) {
    f8 r;
    asm("ld.global.v8.b32 {%0,%1,%2,%3,%4,%5,%6,%7}, [%8];"
        : "=f"(r.a.x), "=f"(r.a.y), "=f"(r.a.z), "=f"(r.a.w),
          "=f"(r.b.x), "=f"(r.b.y), "=f"(r.b.z), "=f"(r.b.w)
        : "l"(p));
    return r;
}

__device__ __forceinline__ void stg256(void* p, f8 v) {
    asm volatile("st.global.v8.b32 [%0], {%1,%2,%3,%4,%5,%6,%7,%8};"
                 :: "l"(p),
                    "f"(v.a.x), "f"(v.a.y), "f"(v.a.z), "f"(v.a.w),
                    "f"(v.b.x), "f"(v.b.y), "f"(v.b.z), "f"(v.b.w)
                 : "memory");
}

__device__ __forceinline__ float dot8(f8 u, f8 v) {
    return u.a.x * v.a.x + u.a.y * v.a.y + u.a.z * v.a.z + u.a.w * v.a.w +
           u.b.x * v.b.x + u.b.y * v.b.y + u.b.z * v.b.z + u.b.w * v.b.w;
}

// o = s0*v0 (+ s1*v1 (+ s2*v2 (+ s3*v3)))  -- helpers to keep code compact
__device__ __forceinline__ float4 comb4(float4 v0, float s0) {
    return make_float4(s0 * v0.x, s0 * v0.y, s0 * v0.z, s0 * v0.w);
}
__device__ __forceinline__ float4 comb4(float4 v0, float s0, float4 v1, float s1) {
    return make_float4(s0 * v0.x + s1 * v1.x, s0 * v0.y + s1 * v1.y,
                       s0 * v0.z + s1 * v1.z, s0 * v0.w + s1 * v1.w);
}
__device__ __forceinline__ float4 comb4(float4 v0, float s0, float4 v1, float s1,
                                        float4 v2, float s2) {
    return make_float4(s0 * v0.x + s1 * v1.x + s2 * v2.x,
                       s0 * v0.y + s1 * v1.y + s2 * v2.y,
                       s0 * v0.z + s1 * v1.z + s2 * v2.z,
                       s0 * v0.w + s1 * v1.w + s2 * v2.w);
}
__device__ __forceinline__ float4 comb4(float4 v0, float s0, float4 v1, float s1,
                                        float4 v2, float s2, float4 v3, float s3) {
    return make_float4(s0 * v0.x + s1 * v1.x + s2 * v2.x + s3 * v3.x,
                       s0 * v0.y + s1 * v1.y + s2 * v2.y + s3 * v3.y,
                       s0 * v0.z + s1 * v1.z + s2 * v2.z + s3 * v3.z,
                       s0 * v0.w + s1 * v1.w + s2 * v2.w + s3 * v3.w);
}

__global__ __launch_bounds__(NTHREADS, 8)
void gram_schmidt_kernel(const float* __restrict__ x, float* __restrict__ out) {
    const int tid  = threadIdx.x;
    const int lane = tid & 31;
    const int warp = tid >> 5;          // 0..3

    __shared__ float red[4][12];             // per-warp partials (padded rows)
    __shared__ __align__(16) float gsm[12];  // final Gram entries

    // byte offset: bc*4096 + tid*32, 32B-aligned, fits unsigned (max < 2^28).
    const unsigned base = blockIdx.x * (D_DIM * 4u) + (unsigned)tid * 32u;
    const char* xb = (const char*)x;
    char* ob = (char*)out;

    // 4 x LDG.256: 1KB contiguous per warp per instruction.
    f8 v0 = ldg256(xb + base);
    f8 v1 = ldg256(xb + base + MSTRIDE_B);
    f8 v2 = ldg256(xb + base + 2u * MSTRIDE_B);
    f8 v3 = ldg256(xb + base + 3u * MSTRIDE_B);

    // 10 pairwise dot partials: (00)(01)(02)(03)(11)(12)(13)(22)(23)(33)
    float p[10];
    p[0] = dot8(v0, v0); p[1] = dot8(v0, v1); p[2] = dot8(v0, v2);
    p[3] = dot8(v0, v3); p[4] = dot8(v1, v1); p[5] = dot8(v1, v2);
    p[6] = dot8(v1, v3); p[7] = dot8(v2, v2); p[8] = dot8(v2, v3);
    p[9] = dot8(v3, v3);

    // Warp butterfly: 10 values packed as 5 x 64-bit shuffles per level.
#pragma unroll
    for (int lvl = 16; lvl >= 1; lvl >>= 1) {
#pragma unroll
        for (int q = 0; q < 5; q++) {
            unsigned long long u =
                ((unsigned long long)__float_as_uint(p[2 * q + 1]) << 32) |
                (unsigned long long)__float_as_uint(p[2 * q]);
            unsigned long long r = __shfl_xor_sync(0xffffffffu, u, lvl);
            p[2 * q]     += __uint_as_float((unsigned)r);
            p[2 * q + 1] += __uint_as_float((unsigned)(r >> 32));
        }
    }

    if (lane == 0) {
        float4* row = reinterpret_cast<float4*>(red[warp]);
        row[0] = make_float4(p[0], p[1], p[2], p[3]);
        row[1] = make_float4(p[4], p[5], p[6], p[7]);
        red[warp][8] = p[8];
        red[warp][9] = p[9];
    }
    __syncthreads();

    // 10 threads finalize across the 4 warps (stride-12 rows: conflict-free).
    if (tid < 10) {
        float s = red[0][tid] + red[1][tid] + red[2][tid] + red[3][tid];
        gsm[tid] = s;
    }
    __syncthreads();

    // Broadcast-read final Gram.
    float4 ga = *reinterpret_cast<const float4*>(gsm);
    float4 gb = *reinterpret_cast<const float4*>(gsm + 4);
    const float g23 = gsm[8], g33 = gsm[9];
    const float g00 = ga.x, g01 = ga.y, g02 = ga.z, g03 = ga.w;
    const float g11 = gb.x, g12 = gb.y, g13 = gb.z, g22 = gb.w;

    // ---- scalar GS recurrence on the Gram matrix (replicated per thread) ----
    const float inv0 = (g00 > 0.f) ? rsqrtf(g00) : 0.f;

    const float c0 = g01 * inv0;
    const float n1 = fmaxf(g11 - c0 * c0, 0.f);
    const float inv1 = (n1 > 0.f) ? rsqrtf(n1) : 0.f;
    const float T10 = -c0 * inv0 * inv1;
    const float T11 = inv1;

    const float d0 = g02 * inv0;
    const float d1 = T10 * g02 + T11 * g12;
    const float n2 = fmaxf(g22 - d0 * d0 - d1 * d1, 0.f);
    const float inv2 = (n2 > 0.f) ? rsqrtf(n2) : 0.f;
    const float T20 = inv2 * (-d0 * inv0 - d1 * T10);
    const float T21 = inv2 * (-d1 * T11);
    const float T22 = inv2;

    const float e0 = g03 * inv0;
    const float e1 = T10 * g03 + T11 * g13;
    const float e2 = T20 * g03 + T21 * g13 + T22 * g23;
    const float n3 = fmaxf(g33 - e0 * e0 - e1 * e1 - e2 * e2, 0.f);
    const float inv3 = (n3 > 0.f) ? rsqrtf(n3) : 0.f;
    const float T30 = inv3 * (-e0 * inv0 - e1 * T10 - e2 * T20);
    const float T31 = inv3 * (-e1 * T11 - e2 * T21);
    const float T32 = inv3 * (-e2 * T22);
    const float T33 = inv3;

    // ---- outputs: basis_i = sum_j T_ij v_j (4 x STG.256) ----
    f8 o;
    o.a = comb4(v0.a, inv0); o.b = comb4(v0.b, inv0);
    stg256(ob + base, o);

    o.a = comb4(v0.a, T10, v1.a, T11); o.b = comb4(v0.b, T10, v1.b, T11);
    stg256(ob + base + MSTRIDE_B, o);

    o.a = comb4(v0.a, T20, v1.a, T21, v2.a, T22);
    o.b = comb4(v0.b, T20, v1.b, T21, v2.b, T22);
    stg256(ob + base + 2u * MSTRIDE_B, o);

    o.a = comb4(v0.a, T30, v1.a, T31, v2.a, T32, v3.a, T33);
    o.b = comb4(v0.b, T30, v1.b, T31, v2.b, T32, v3.b, T33);
    stg256(ob + base + 3u * MSTRIDE_B, o);
}

extern "C" void kernel_launch(void* const* d_in, const int* in_sizes, int n_in,
                              void* d_out, int out_size) {
    const float* x = (const float*)d_in[0];
    float* out = (float*)d_out;
    gram_schmidt_kernel<<<NPAIRS, NTHREADS>>>(x, out);
}